// round 16
// baseline (speedup 1.0000x reference)
#include <cuda_runtime.h>
#include <cuda_bf16.h>
#include <math.h>
#include <stdint.h>

// ---------------- problem constants ----------------
#define NB   8
#define LL   512
#define DD   256
#define HH   16
#define QK   32
#define VD   32
#define OUTD 256
#define NL   (NB*LL)          // 4096
#define QKH  (QK*HH)          // 512
#define FEAT 640              // 512 node + 128 spatial
#define HID  512              // OUT*2
#define LOG2E 1.4426950408889634f

// ---------------- bf16 / async helpers ----------------
__device__ __forceinline__ uint32_t bf2(float lo, float hi) {
    uint32_t d;
    asm("cvt.rn.bf16x2.f32 %0, %1, %2;" : "=r"(d) : "f"(hi), "f"(lo));
    return d;
}
__device__ __forceinline__ void mma_bf16(float c[4],
                                         uint32_t a0, uint32_t a1, uint32_t a2, uint32_t a3,
                                         uint32_t b0, uint32_t b1) {
    asm volatile("mma.sync.aligned.m16n8k16.row.col.f32.bf16.bf16.f32 "
                 "{%0,%1,%2,%3}, {%4,%5,%6,%7}, {%8,%9}, {%0,%1,%2,%3};"
                 : "+f"(c[0]), "+f"(c[1]), "+f"(c[2]), "+f"(c[3])
                 : "r"(a0), "r"(a1), "r"(a2), "r"(a3), "r"(b0), "r"(b1));
}
__device__ __forceinline__ uint2 ldsm2t(const void* p) {   // transposed x2
    uint32_t a = (uint32_t)__cvta_generic_to_shared(p);
    uint2 r;
    asm volatile("ldmatrix.sync.aligned.m8n8.x2.trans.shared.b16 {%0,%1}, [%2];"
                 : "=r"(r.x), "=r"(r.y) : "r"(a));
    return r;
}
__device__ __forceinline__ uint2 ldsm2(const void* p) {    // non-trans x2
    uint32_t a = (uint32_t)__cvta_generic_to_shared(p);
    uint2 r;
    asm volatile("ldmatrix.sync.aligned.m8n8.x2.shared.b16 {%0,%1}, [%2];"
                 : "=r"(r.x), "=r"(r.y) : "r"(a));
    return r;
}
__device__ __forceinline__ uint4 ldsm4(const void* p) {    // non-trans x4 (A m16k16)
    uint32_t a = (uint32_t)__cvta_generic_to_shared(p);
    uint4 r;
    asm volatile("ldmatrix.sync.aligned.m8n8.x4.shared.b16 {%0,%1,%2,%3}, [%4];"
                 : "=r"(r.x), "=r"(r.y), "=r"(r.z), "=r"(r.w) : "r"(a));
    return r;
}
__device__ __forceinline__ void cpa16(void* s, const void* g) {
    uint32_t a = (uint32_t)__cvta_generic_to_shared(s);
    asm volatile("cp.async.ca.shared.global [%0], [%1], 16;" :: "r"(a), "l"(g));
}
#define CP_COMMIT asm volatile("cp.async.commit_group;" ::: "memory")
#define CP_WAIT0  asm volatile("cp.async.wait_group 0;" ::: "memory")
#define CP_WAIT1  asm volatile("cp.async.wait_group 1;" ::: "memory")

// 2^y via FMA-only, degree-4 Taylor (|rel err| ~3e-5)
__device__ __forceinline__ float fexp2(float y) {
    float r = y + 12582912.0f;                    // round to int (1.5*2^23)
    int   n = __float_as_int(r) - 0x4B400000;
    float f = y - (r - 12582912.0f);              // f in [-0.5, 0.5]
    float p = 9.6181291076e-3f;
    p = fmaf(p, f, 5.5504108665e-2f);
    p = fmaf(p, f, 2.4022650696e-1f);
    p = fmaf(p, f, 6.9314718056e-1f);
    p = fmaf(p, f, 1.0f);
    return __int_as_float(__float_as_int(p) + (n << 23));
}

// ---------------- scratch (no allocs allowed) ----------------
__device__ uint32_t g_qb[(size_t)NL*QKH/2];     // bf16x2 packed; q pre-scaled by log2(e)
__device__ uint32_t g_kb[(size_t)NL*QKH/2];
__device__ uint32_t g_vb[(size_t)NL*QKH/2];     // V rows pre-masked (zero where !mask)
__device__ uint32_t g_h1b[(size_t)NL*HID/2];
__device__ uint32_t g_featb[(size_t)NL*FEAT/2];
__device__ uint32_t g_xb[(size_t)NL*DD/2];
__device__ uint32_t g_tb[(size_t)NL*QK/2];
__device__ float    g_y[(size_t)NL*OUTD];
// bf16 weights [k][n] (converted once per launch)
__device__ uint32_t g_wq[DD*QKH/2];
__device__ uint32_t g_wk[DD*QKH/2];
__device__ uint32_t g_wv[DD*QKH/2];
__device__ uint32_t g_wse[QK*QKH/2];
__device__ uint32_t g_w1[FEAT*HID/2];
__device__ uint32_t g_w2[HID*OUTD/2];

// ============================================================
// K-1: convert weights + x  fp32 -> packed bf16
// ============================================================
__global__ void k_cvtw(const float* __restrict__ Wq, const float* __restrict__ Wk,
                       const float* __restrict__ Wv, const float* __restrict__ seW2,
                       const float* __restrict__ W1, const float* __restrict__ W2,
                       const float* __restrict__ x)
{
    const int m = blockIdx.y;
    const float* src; uint32_t* dst; int ng;   // groups of 8 elements
    switch (m) {
        case 0: src = Wq;   dst = g_wq;  ng = DD*QKH/8;   break;
        case 1: src = Wk;   dst = g_wk;  ng = DD*QKH/8;   break;
        case 2: src = Wv;   dst = g_wv;  ng = DD*QKH/8;   break;
        case 3: src = seW2; dst = g_wse; ng = QK*QKH/8;   break;
        case 4: src = W1;   dst = g_w1;  ng = FEAT*HID/8; break;
        case 5: src = W2;   dst = g_w2;  ng = HID*OUTD/8; break;
        default:src = x;    dst = g_xb;  ng = NL*DD/8;    break;
    }
    int i = blockIdx.x * blockDim.x + threadIdx.x;
    if (i >= ng) return;
    float4 a = ((const float4*)src)[2*i];
    float4 b = ((const float4*)src)[2*i+1];
    uint4 w;
    w.x = bf2(a.x, a.y); w.y = bf2(a.z, a.w);
    w.z = bf2(b.x, b.y); w.w = bf2(b.z, b.w);
    ((uint4*)dst)[i] = w;
}

// ============================================================
// K0: t = relu(pos_CA @ se_W1 + se_b1) -> packed bf16 (4096x32)
// ============================================================
__global__ void k_spat(const float* __restrict__ posCA,
                       const float* __restrict__ seW1,
                       const float* __restrict__ seb1)
{
    int r = blockIdx.x * blockDim.x + threadIdx.x;
    if (r >= NL) return;
    float p0 = posCA[r*3+0], p1 = posCA[r*3+1], p2 = posCA[r*3+2];
#pragma unroll
    for (int j = 0; j < QK/2; j++) {
        int c0 = 2*j, c1 = 2*j+1;
        float v0 = seb1[c0] + p0*seW1[c0] + p1*seW1[QK + c0] + p2*seW1[2*QK + c0];
        float v1 = seb1[c1] + p0*seW1[c1] + p1*seW1[QK + c1] + p2*seW1[2*QK + c1];
        g_tb[(size_t)r*(QK/2) + j] = bf2(fmaxf(v0, 0.0f), fmaxf(v1, 0.0f));
    }
}

// ============================================================
// GEMM: BM=128, BN=64, BK=32, 8 warps (2M x 4N), m16n8k16.
// cp.async double-buffered; A fragments via ldmatrix.x4.
// ============================================================
__device__ __forceinline__ void loadA_async(uint32_t (*As)[20], const uint32_t* A,
                                            int ldp, int bm, int kcp, int tid)
{
    int r = tid >> 1;
    int h = (tid & 1) * 8;
    const uint32_t* p = A + (size_t)(bm + r) * ldp + kcp + h;
    cpa16(&As[r][h],     p);
    cpa16(&As[r][h + 4], p + 4);
}
__device__ __forceinline__ void loadB_async(__nv_bfloat16 (*Bs16)[72], const uint32_t* W,
                                            int ldn2, int bn, int kc, int tid)
{
    int k  = tid >> 3;
    int n0 = (tid & 7) * 8;
    cpa16(&Bs16[k][n0], W + (size_t)(kc + k) * ldn2 + (bn + n0)/2);
}

__device__ __forceinline__ void mma_chunk_bf(const uint32_t (*As)[20],
                                             const __nv_bfloat16 (*Bs16)[72],
                                             float acc[4][2][4], int warpM, int warpN,
                                             int lane)
{
    const int i16 = lane & 15;
    const int hi4 = (lane >> 4) * 4;   // u32 (pair) offset for ldsm4 col window
#pragma unroll
    for (int s = 0; s < 2; s++) {
        uint2 b[2];
#pragma unroll
        for (int nt = 0; nt < 2; nt++)
            b[nt] = ldsm2t(&Bs16[s*16 + i16][warpN*16 + nt*8]);
#pragma unroll
        for (int mt = 0; mt < 4; mt++) {
            uint4 a = ldsm4(&As[warpM*64 + mt*16 + i16][s*8 + hi4]);
#pragma unroll
            for (int nt = 0; nt < 2; nt++)
                mma_bf16(acc[mt][nt], a.x, a.y, a.z, a.w, b[nt].x, b[nt].y);
        }
    }
}

#define GEMM_PROLOG                                                  \
    __shared__ __align__(16) uint32_t AsB[2][128][20];               \
    __shared__ __align__(16) __nv_bfloat16 BsB[2][32][72];           \
    const int tid  = threadIdx.x;                                    \
    const int wid  = tid >> 5;                                       \
    const int lane = tid & 31;                                       \
    const int g    = lane >> 2, t4 = lane & 3;                       \
    const int warpM = wid >> 2, warpN = wid & 3;                     \
    float acc[4][2][4];                                              \
    _Pragma("unroll") for (int i = 0; i < 4; i++)                    \
    _Pragma("unroll") for (int j = 0; j < 2; j++)                    \
    _Pragma("unroll") for (int q = 0; q < 4; q++) acc[i][j][q] = 0.0f;

// ============================================================
// K1: fused QKV projection (4096 x 1536, K=256).
// q: + t@se_W2 + se_b2, then *log2(e).  v: pre-masked by row mask.
// ============================================================
__global__ void __launch_bounds__(256) k_qkv(const float* __restrict__ seb2,
                                             const int* __restrict__ mask)
{
    const int bm  = blockIdx.x * 128;
    const int mat = blockIdx.y >> 3;           // 0=q 1=k 2=v
    const int bn  = (blockIdx.y & 7) * 64;
    const uint32_t* W = (mat == 0) ? g_wq : (mat == 1) ? g_wk : g_wv;

    GEMM_PROLOG
    (void)g; (void)t4;

    const int nchunks = (mat == 0) ? 9 : 8;
    loadA_async(AsB[0], g_xb, DD/2, bm, 0, tid);
    loadB_async(BsB[0], W, QKH/2, bn, 0, tid);
    CP_COMMIT;
    for (int ch = 0; ch < nchunks; ch++) {
        if (ch + 1 < nchunks) {
            int nb = (ch + 1) & 1;
            if (ch + 1 < 8) {
                loadA_async(AsB[nb], g_xb, DD/2, bm, (ch+1)*16, tid);
                loadB_async(BsB[nb], W, QKH/2, bn, (ch+1)*32, tid);
            } else {
                loadA_async(AsB[nb], g_tb, QK/2, bm, 0, tid);
                loadB_async(BsB[nb], g_wse, QKH/2, bn, 0, tid);
            }
            CP_COMMIT;
            CP_WAIT1;
        } else {
            CP_WAIT0;
        }
        __syncthreads();
        mma_chunk_bf(AsB[ch & 1], BsB[ch & 1], acc, warpM, warpN, lane);
        __syncthreads();
    }

    uint32_t* dst = (mat == 0) ? g_qb : (mat == 1) ? g_kb : g_vb;
    const int gg = lane >> 2, tt = lane & 3;
#pragma unroll
    for (int mt = 0; mt < 4; mt++) {
#pragma unroll
        for (int nt = 0; nt < 2; nt++) {
            int R0 = bm + warpM*64 + mt*16 + gg;
            int C  = bn + warpN*16 + nt*8 + 2*tt;
            float v0 = acc[mt][nt][0], v1 = acc[mt][nt][1];
            float v2 = acc[mt][nt][2], v3 = acc[mt][nt][3];
            if (mat == 0) {
                float bx = seb2[C], by = seb2[C+1];
                v0 = (v0 + bx) * LOG2E; v1 = (v1 + by) * LOG2E;
                v2 = (v2 + bx) * LOG2E; v3 = (v3 + by) * LOG2E;
            } else if (mat == 2) {
                float m0 = mask[R0]     ? 1.0f : 0.0f;
                float m1 = mask[R0 + 8] ? 1.0f : 0.0f;
                v0 *= m0; v1 *= m0; v2 *= m1; v3 *= m1;
            }
            dst[(size_t)R0*(QKH/2)     + C/2] = bf2(v0, v1);
            dst[(size_t)(R0+8)*(QKH/2) + C/2] = bf2(v2, v3);
        }
    }
}

// ============================================================
// K2: bf16 TC attention, q-split, cp.async pipeline,
// register-resident P (no inner-loop masking: V pre-masked,
// augmented cols masked at write), Q in regs, exp2 pre-scaled q.
// Grid (HH, NB, 2): block = 256 q-rows of one (b,h), 8 warps.
// ============================================================
__global__ void __launch_bounds__(256, 2) k_attn(
    const float* __restrict__ posCA,
    const float* __restrict__ posCB,
    const float* __restrict__ frame,
    const int*   __restrict__ mask)
{
    extern __shared__ __align__(16) uint32_t smu[];
    uint32_t (*Qs)[20] = (uint32_t (*)[20])smu;                              // [256][20]
    uint32_t (*KsB)[32][20] = (uint32_t (*)[32][20])(smu + 256*20);          // [2][32][20]
    __nv_bfloat16 (*VsB)[32][72] = (__nv_bfloat16 (*)[32][72])(smu + 256*20 + 2*32*20); // [2][32][72]
    float* mkf = (float*)(smu + 256*20 + 2*32*20 + 2*32*36);                 // [512]

    const int h  = blockIdx.x;
    const int b  = blockIdx.y;
    const int qh = blockIdx.z;
    const int tid = threadIdx.x;
    const int w = tid >> 5, lane = tid & 31;
    const int g = lane >> 2, t4 = lane & 3;
    const int i16 = lane & 15;
    const int krow = lane & 7, khalf = (lane >> 3) & 1;   // ldmatrix.x2 addressing
    const int qbase = qh * 256;

    // ---- group 0: Q + K/V chunk 0 ----
#pragma unroll
    for (int it = 0; it < 4; it++) {
        int idx = tid + 256*it;
        int r = idx >> 2, c4 = idx & 3;
        cpa16(&Qs[r][c4*4], g_qb + ((size_t)b*LL + qbase + r)*(QKH/2) + h*(QK/2) + c4*4);
    }
    if (tid < 128) {
        int j = tid >> 2, c4 = tid & 3;
        cpa16(&VsB[0][j][c4*8], g_vb + ((size_t)b*LL + j)*(QKH/2) + h*(QK/2) + c4*4);
    } else {
        int t = tid - 128;
        int j = t >> 2, c4 = t & 3;
        cpa16(&KsB[0][j][c4*4], g_kb + ((size_t)b*LL + j)*(QKH/2) + h*(QK/2) + c4*4);
    }
    CP_COMMIT;
    if (tid < 32) {
        int j = tid;
        float mj = mask[b*LL + j] ? 1.0f : 0.0f;
        const float* pp = posCB + ((size_t)b*LL + j)*3;
        VsB[0][j][32] = __float2bfloat16(mj * pp[0]);
        VsB[0][j][33] = __float2bfloat16(mj * pp[1]);
        VsB[0][j][34] = __float2bfloat16(mj * pp[2]);
        VsB[0][j][35] = __float2bfloat16(mj);
        VsB[0][j][36] = __float2bfloat16(0.0f);
        VsB[0][j][37] = __float2bfloat16(0.0f);
        VsB[0][j][38] = __float2bfloat16(0.0f);
        VsB[0][j][39] = __float2bfloat16(0.0f);
    }
    mkf[tid]       = mask[b*LL + tid]       ? 1.0f : 0.0f;
    mkf[tid + 256] = mask[b*LL + tid + 256] ? 1.0f : 0.0f;

    // ---- group 1: K/V chunk 1 ----
    if (tid < 128) {
        int j = tid >> 2, c4 = tid & 3;
        cpa16(&VsB[1][j][c4*8], g_vb + ((size_t)b*LL + 32 + j)*(QKH/2) + h*(QK/2) + c4*4);
    } else {
        int t = tid - 128;
        int j = t >> 2, c4 = t & 3;
        cpa16(&KsB[1][j][c4*4], g_kb + ((size_t)b*LL + 32 + j)*(QKH/2) + h*(QK/2) + c4*4);
    }
    CP_COMMIT;
    if (tid < 32) {
        int j = tid;
        float mj = mask[b*LL + 32 + j] ? 1.0f : 0.0f;
        const float* pp = posCB + ((size_t)b*LL + 32 + j)*3;
        VsB[1][j][32] = __float2bfloat16(mj * pp[0]);
        VsB[1][j][33] = __float2bfloat16(mj * pp[1]);
        VsB[1][j][34] = __float2bfloat16(mj * pp[2]);
        VsB[1][j][35] = __float2bfloat16(mj);
        VsB[1][j][36] = __float2bfloat16(0.0f);
        VsB[1][j][37] = __float2bfloat16(0.0f);
        VsB[1][j][38] = __float2bfloat16(0.0f);
        VsB[1][j][39] = __float2bfloat16(0.0f);
    }
    CP_WAIT1;        // group 0 (Q + chunk 0) complete
    __syncthreads();

    // ---- hoist Q fragments into registers (chunk-invariant) ----
    uint32_t qreg[2][2][4];
#pragma unroll
    for (int mt = 0; mt < 2; mt++) {
        const int rb = w*32 + mt*16;
#pragma unroll
        for (int s = 0; s < 2; s++) {
            qreg[mt][s][0] = Qs[rb+g][s*8+t4];
            qreg[mt][s][1] = Qs[rb+g+8][s*8+t4];
            qreg[mt][s][2] = Qs[rb+g][s*8+t4+4];
            qreg[mt][s][3] = Qs[rb+g+8][s*8+t4+4];
        }
    }

    float acc[2][5][4];
#pragma unroll
    for (int i = 0; i < 2; i++)
#pragma unroll
        for (int j = 0; j < 5; j++)
#pragma unroll
            for (int q = 0; q < 4; q++) acc[i][j][q] = 0.0f;

    for (int ch = 0; ch < 16; ch++) {
        const int cb = ch & 1;

        // K fragments via ldmatrix.x2 (non-trans on [n][k] layout)
        uint32_t kb[4][2][2];
#pragma unroll
        for (int nt = 0; nt < 4; nt++)
#pragma unroll
            for (int s = 0; s < 2; s++) {
                uint2 t = ldsm2(&KsB[cb][8*nt + krow][s*8 + khalf*4]);
                kb[nt][s][0] = t.x;
                kb[nt][s][1] = t.y;
            }
        // V fragments
        uint2 vb[2][5];
#pragma unroll
        for (int s = 0; s < 2; s++)
#pragma unroll
            for (int nt = 0; nt < 5; nt++)
                vb[s][nt] = ldsm2t(&VsB[cb][s*16 + i16][nt*8]);

#pragma unroll
        for (int mt = 0; mt < 2; mt++) {
            // ---- S = Q @ K^T  (q pre-scaled: S is log2-domain) ----
            float S[4][4];
#pragma unroll
            for (int nt = 0; nt < 4; nt++)
#pragma unroll
                for (int q = 0; q < 4; q++) S[nt][q] = 0.0f;
#pragma unroll
            for (int s = 0; s < 2; s++)
#pragma unroll
                for (int nt = 0; nt < 4; nt++)
                    mma_bf16(S[nt], qreg[mt][s][0], qreg[mt][s][1],
                             qreg[mt][s][2], qreg[mt][s][3],
                             kb[nt][s][0], kb[nt][s][1]);
            // ---- P = exp2(S) (mask folded into V), packed as A fragments ----
            uint32_t pa[2][4];
#pragma unroll
            for (int hf = 0; hf < 2; hf++) {
                const int na = 2*hf, nb2 = 2*hf + 1;
                pa[hf][0] = bf2(fexp2(S[na][0]),  fexp2(S[na][1]));
                pa[hf][1] = bf2(fexp2(S[na][2]),  fexp2(S[na][3]));
                pa[hf][2] = bf2(fexp2(S[nb2][0]), fexp2(S[nb2][1]));
                pa[hf][3] = bf2(fexp2(S[nb2][2]), fexp2(S[nb2][3]));
            }
            // ---- O += P @ Vaug ----
#pragma unroll
            for (int s = 0; s < 2; s++)
#pragma unroll
                for (int nt = 0; nt < 5; nt++)
                    mma_bf16(acc[mt][nt], pa[s][0], pa[s][1], pa[s][2], pa[s][3],
                             vb[s][nt].x, vb[s][nt].y);
        }

        __syncthreads();   // all warps done reading buffer cb
        if (ch + 2 < 16) {
            const int j2 = (ch + 2) * 32;
            if (tid < 128) {
                int j = tid >> 2, c4 = tid & 3;
                cpa16(&VsB[cb][j][c4*8], g_vb + ((size_t)b*LL + j2 + j)*(QKH/2) + h*(QK/2) + c4*4);
            } else {
                int t = tid - 128;
                int j = t >> 2, c4 = t & 3;
                cpa16(&KsB[cb][j][c4*4], g_kb + ((size_t)b*LL + j2 + j)*(QKH/2) + h*(QK/2) + c4*4);
            }
            CP_COMMIT;
            if (tid < 32) {
                int j = tid;
                float mj = mask[b*LL + j2 + j] ? 1.0f : 0.0f;
                const float* pp = posCB + ((size_t)b*LL + j2 + j)*3;
                VsB[cb][j][32] = __float2bfloat16(mj * pp[0]);
                VsB[cb][j][33] = __float2bfloat16(mj * pp[1]);
                VsB[cb][j][34] = __float2bfloat16(mj * pp[2]);
                VsB[cb][j][35] = __float2bfloat16(mj);
                VsB[cb][j][36] = __float2bfloat16(0.0f);
                VsB[cb][j][37] = __float2bfloat16(0.0f);
                VsB[cb][j][38] = __float2bfloat16(0.0f);
                VsB[cb][j][39] = __float2bfloat16(0.0f);
            }
        }
        if (ch + 1 < 16) {
            if (ch + 2 < 16) { CP_WAIT1; } else { CP_WAIT0; }
            __syncthreads();
        }
    }

    // ---- epilogue (fp32 math, bf16 feature stores) ----
#pragma unroll
    for (int mt = 0; mt < 2; mt++) {
#pragma unroll
        for (int half = 0; half < 2; half++) {
            const int rloc = w*32 + mt*16 + g + half*8;
            const size_t grow = (size_t)b*LL + qbase + rloc;
            float c_lo = half ? acc[mt][4][2] : acc[mt][4][0];
            float c_hi = half ? acc[mt][4][3] : acc[mt][4][1];
            const int qb = lane & ~3;
            float ap0 = __shfl_sync(0xffffffffu, c_lo, qb + 0);
            float ap1 = __shfl_sync(0xffffffffu, c_hi, qb + 0);
            float ap2 = __shfl_sync(0xffffffffu, c_lo, qb + 1);
            float s   = __shfl_sync(0xffffffffu, c_hi, qb + 1);
            const bool ok = (mkf[qbase + rloc] != 0.0f) && (s > 0.0f);
            const float inv = ok ? 1.0f / s : 0.0f;
            uint32_t* fr = g_featb + grow * (FEAT/2);
            __nv_bfloat16* fr16 = (__nv_bfloat16*)fr;
#pragma unroll
            for (int nt = 0; nt < 4; nt++) {
                float v0 = half ? acc[mt][nt][2] : acc[mt][nt][0];
                float v1 = half ? acc[mt][nt][3] : acc[mt][nt][1];
                fr[h*16 + nt*4 + t4] = bf2(v0*inv, v1*inv);
            }
            if (t4 == 0) {
                if (!ok) {
                    fr16[512+h*3+0] = __float2bfloat16(0.0f);
                    fr16[512+h*3+1] = __float2bfloat16(0.0f);
                    fr16[512+h*3+2] = __float2bfloat16(0.0f);
                    fr16[560+h]     = __float2bfloat16(0.0f);
                    fr16[576+h*3+0] = __float2bfloat16(0.0f);
                    fr16[576+h*3+1] = __float2bfloat16(0.0f);
                    fr16[576+h*3+2] = __float2bfloat16(0.0f);
                    fr16[624+h]     = __float2bfloat16(0.0f);
                } else {
                    float a0 = ap0*inv - posCA[grow*3+0];
                    float a1 = ap1*inv - posCA[grow*3+1];
                    float a2 = ap2*inv - posCA[grow*3+2];
                    const float* F = frame + grow * 9;
                    float pt0 = F[0]*a0 + F[1]*a1 + F[2]*a2;
                    float pt1 = F[3]*a0 + F[4]*a1 + F[5]*a2;
                    float pt2 = F[6]*a0 + F[7]*a1 + F[8]*a2;
                    float dist = sqrtf(a0*a0 + a1*a1 + a2*a2);
                    float pn   = sqrtf(pt0*pt0 + pt1*pt1 + pt2*pt2);
                    float id   = 1.0f / (pn + 1e-10f);
                    float ang  = atan2f(pt1, pt0);
                    fr16[512+h*3+0] = __float2bfloat16(pt0);
                    fr16[512+h*3+1] = __float2bfloat16(pt1);
                    fr16[512+h*3+2] = __float2bfloat16(pt2);
                    fr16[560+h]     = __float2bfloat16(dist);
                    fr16[576+h*3+0] = __float2bfloat16(pt0*id);
                    fr16[576+h*3+1] = __float2bfloat16(pt1*id);
                    fr16[576+h*3+2] = __float2bfloat16(pt2*id);
                    fr16[624+h]     = __float2bfloat16(ang);
                }
            }
        }
    }
}

// ============================================================
// K3a: h1 = relu(feat @ W1 + b1) -> packed bf16 (4096x512,K=640)
// ============================================================
__global__ void __launch_bounds__(256) k_mlp1(const float* __restrict__ b1)
{
    const int bm = blockIdx.x * 128;
    const int bn = blockIdx.y * 64;

    GEMM_PROLOG

    const int NCH = FEAT/32;   // 20
    loadA_async(AsB[0], g_featb, FEAT/2, bm, 0, tid);
    loadB_async(BsB[0], g_w1, HID/2, bn, 0, tid);
    CP_COMMIT;
    for (int ch = 0; ch < NCH; ch++) {
        if (ch + 1 < NCH) {
            int nb = (ch + 1) & 1;
            loadA_async(AsB[nb], g_featb, FEAT/2, bm, (ch+1)*16, tid);
            loadB_async(BsB[nb], g_w1, HID/2, bn, (ch+1)*32, tid);
            CP_COMMIT;
            CP_WAIT1;
        } else {
            CP_WAIT0;
        }
        __syncthreads();
        mma_chunk_bf(AsB[ch & 1], BsB[ch & 1], acc, warpM, warpN, lane);
        __syncthreads();
    }

#pragma unroll
    for (int mt = 0; mt < 4; mt++) {
#pragma unroll
        for (int nt = 0; nt < 2; nt++) {
            int R0 = bm + warpM*64 + mt*16 + g;
            int C  = bn + warpN*16 + nt*8 + 2*t4;
            float bx = b1[C], by = b1[C+1];
            g_h1b[(size_t)R0*(HID/2)     + C/2] =
                bf2(fmaxf(acc[mt][nt][0] + bx, 0.f), fmaxf(acc[mt][nt][1] + by, 0.f));
            g_h1b[(size_t)(R0+8)*(HID/2) + C/2] =
                bf2(fmaxf(acc[mt][nt][2] + bx, 0.f), fmaxf(acc[mt][nt][3] + by, 0.f));
        }
    }
}

// ============================================================
// K3b: y = x + mask*(h1 @ W2 + b2)   (4096x256, K=512)
// ============================================================
__global__ void __launch_bounds__(256) k_mlp2(
    const float* __restrict__ x, const float* __restrict__ b2,
    const int* __restrict__ mask)
{
    const int bm = blockIdx.x * 128;
    const int bn = blockIdx.y * 64;

    GEMM_PROLOG

    const int NCH = HID/32;   // 16
    loadA_async(AsB[0], g_h1b, HID/2, bm, 0, tid);
    loadB_async(BsB[0], g_w2, OUTD/2, bn, 0, tid);
    CP_COMMIT;
    for (int ch = 0; ch < NCH; ch++) {
        if (ch + 1 < NCH) {
            int nb = (ch + 1) & 1;
            loadA_async(AsB[nb], g_h1b, HID/2, bm, (ch+1)*16, tid);
            loadB_async(BsB[nb], g_w2, OUTD/2, bn, (ch+1)*32, tid);
            CP_COMMIT;
            CP_WAIT1;
        } else {
            CP_WAIT0;
        }
        __syncthreads();
        mma_chunk_bf(AsB[ch & 1], BsB[ch & 1], acc, warpM, warpN, lane);
        __syncthreads();
    }

#pragma unroll
    for (int mt = 0; mt < 4; mt++) {
#pragma unroll
        for (int nt = 0; nt < 2; nt++) {
            int R0 = bm + warpM*64 + mt*16 + g;
            int C  = bn + warpN*16 + nt*8 + 2*t4;
            float bx = b2[C], by = b2[C+1];
#pragma unroll
            for (int half = 0; half < 2; half++) {
                int R = R0 + half*8;
                float2 xv = *(const float2*)&x[(size_t)R*OUTD + C];
                float2 v;
                if (mask[R]) {
                    v.x = xv.x + acc[mt][nt][2*half+0] + bx;
                    v.y = xv.y + acc[mt][nt][2*half+1] + by;
                } else {
                    v = xv;
                }
                *(float2*)&g_y[(size_t)R*OUTD + C] = v;
            }
        }
    }
}

// ============================================================
// K4: LayerNorm. One warp per row.
// ============================================================
__global__ void __launch_bounds__(256) k_ln(
    const float* __restrict__ lng, const float* __restrict__ lnb,
    float* __restrict__ out)
{
    const int wid  = threadIdx.x >> 5;
    const int lane = threadIdx.x & 31;
    const int row  = blockIdx.x * 8 + wid;

    const float* yr = g_y + (size_t)row * OUTD;
    float yv[8];
    float ssum = 0.0f, ssq = 0.0f;
#pragma unroll
    for (int t = 0; t < 2; t++) {
        float4 v = *(const float4*)&yr[lane*4 + t*128];
        yv[t*4+0]=v.x; yv[t*4+1]=v.y; yv[t*4+2]=v.z; yv[t*4+3]=v.w;
        ssum += v.x+v.y+v.z+v.w;
        ssq  += v.x*v.x+v.y*v.y+v.z*v.z+v.w*v.w;
    }
#pragma unroll
    for (int off = 16; off > 0; off >>= 1) {
        ssum += __shfl_xor_sync(0xFFFFFFFF, ssum, off);
        ssq  += __shfl_xor_sync(0xFFFFFFFF, ssq,  off);
    }
    float mu  = ssum * (1.0f / OUTD);
    float var = ssq * (1.0f / OUTD) - mu * mu;
    float rs  = rsqrtf(var + 1e-5f);
#pragma unroll
    for (int t = 0; t < 2; t++) {
        int c = lane*4 + t*128;
        float4 gg = *(const float4*)&lng[c];
        float4 bb = *(const float4*)&lnb[c];
        float4 o;
        o.x = (yv[t*4+0]-mu)*rs*gg.x + bb.x;
        o.y = (yv[t*4+1]-mu)*rs*gg.y + bb.y;
        o.z = (yv[t*4+2]-mu)*rs*gg.z + bb.z;
        o.w = (yv[t*4+3]-mu)*rs*gg.w + bb.w;
        *(float4*)&out[(size_t)row*OUTD + c] = o;
    }
}

// ============================================================
extern "C" void kernel_launch(void* const* d_in, const int* in_sizes, int n_in,
                              void* d_out, int out_size)
{
    const float* x     = (const float*)d_in[0];
    const float* posCA = (const float*)d_in[1];
    const float* posCB = (const float*)d_in[2];
    const float* frame = (const float*)d_in[3];
    const int*   mask  = (const int*)  d_in[4];
    const float* Wq    = (const float*)d_in[5];
    const float* Wk    = (const float*)d_in[6];
    const float* Wv    = (const float*)d_in[7];
    const float* seW1  = (const float*)d_in[8];
    const float* seb1  = (const float*)d_in[9];
    const float* seW2  = (const float*)d_in[10];
    const float* seb2  = (const float*)d_in[11];
    const float* otW1  = (const float*)d_in[12];
    const float* otb1  = (const float*)d_in[13];
    const float* otW2  = (const float*)d_in[14];
    const float* otb2  = (const float*)d_in[15];
    const float* lng   = (const float*)d_in[16];
    const float* lnb   = (const float*)d_in[17];
    float* out = (float*)d_out;

    // Qs + 2xKs (u32) + 2xVs (halves) + mkf
    const int smem_attn = (256*20 + 2*32*20) * 4 + 2*32*72*2 + 512*4;  // 36864
    cudaFuncSetAttribute(k_attn, cudaFuncAttributeMaxDynamicSharedMemorySize, smem_attn);

    k_cvtw<<<dim3(512, 7), 256>>>(Wq, Wk, Wv, seW2, otW1, otW2, x);
    k_spat<<<NL/128, 128>>>(posCA, seW1, seb1);
    k_qkv<<<dim3(NL/128, 24), 256>>>(seb2, mask);
    k_attn<<<dim3(HH, NB, 2), 256, smem_attn>>>(posCA, posCB, frame, mask);
    k_mlp1<<<dim3(NL/128, HID/64),  256>>>(otb1);
    k_mlp2<<<dim3(NL/128, OUTD/64), 256>>>(x, otb2, mask);
    k_ln<<<NL/8, 256>>>(lng, lnb, out);
}

// round 17
// speedup vs baseline: 1.0565x; 1.0565x over previous
#include <cuda_runtime.h>
#include <cuda_bf16.h>
#include <math.h>
#include <stdint.h>

// ---------------- problem constants ----------------
#define NB   8
#define LL   512
#define DD   256
#define HH   16
#define QK   32
#define VD   32
#define OUTD 256
#define NL   (NB*LL)          // 4096
#define QKH  (QK*HH)          // 512
#define FEAT 640              // 512 node + 128 spatial
#define HID  512              // OUT*2
#define LOG2E 1.4426950408889634f

// ---------------- bf16 / async helpers ----------------
__device__ __forceinline__ uint32_t bf2(float lo, float hi) {
    uint32_t d;
    asm("cvt.rn.bf16x2.f32 %0, %1, %2;" : "=r"(d) : "f"(hi), "f"(lo));
    return d;
}
__device__ __forceinline__ void mma_bf16(float c[4],
                                         uint32_t a0, uint32_t a1, uint32_t a2, uint32_t a3,
                                         uint32_t b0, uint32_t b1) {
    asm volatile("mma.sync.aligned.m16n8k16.row.col.f32.bf16.bf16.f32 "
                 "{%0,%1,%2,%3}, {%4,%5,%6,%7}, {%8,%9}, {%0,%1,%2,%3};"
                 : "+f"(c[0]), "+f"(c[1]), "+f"(c[2]), "+f"(c[3])
                 : "r"(a0), "r"(a1), "r"(a2), "r"(a3), "r"(b0), "r"(b1));
}
__device__ __forceinline__ uint2 ldsm2t(const void* p) {   // transposed x2
    uint32_t a = (uint32_t)__cvta_generic_to_shared(p);
    uint2 r;
    asm volatile("ldmatrix.sync.aligned.m8n8.x2.trans.shared.b16 {%0,%1}, [%2];"
                 : "=r"(r.x), "=r"(r.y) : "r"(a));
    return r;
}
__device__ __forceinline__ uint2 ldsm2(const void* p) {    // non-trans x2
    uint32_t a = (uint32_t)__cvta_generic_to_shared(p);
    uint2 r;
    asm volatile("ldmatrix.sync.aligned.m8n8.x2.shared.b16 {%0,%1}, [%2];"
                 : "=r"(r.x), "=r"(r.y) : "r"(a));
    return r;
}
__device__ __forceinline__ uint4 ldsm4(const void* p) {    // non-trans x4 (A m16k16)
    uint32_t a = (uint32_t)__cvta_generic_to_shared(p);
    uint4 r;
    asm volatile("ldmatrix.sync.aligned.m8n8.x4.shared.b16 {%0,%1,%2,%3}, [%4];"
                 : "=r"(r.x), "=r"(r.y), "=r"(r.z), "=r"(r.w) : "r"(a));
    return r;
}
__device__ __forceinline__ void cpa16(void* s, const void* g) {
    uint32_t a = (uint32_t)__cvta_generic_to_shared(s);
    asm volatile("cp.async.ca.shared.global [%0], [%1], 16;" :: "r"(a), "l"(g));
}
#define CP_COMMIT asm volatile("cp.async.commit_group;" ::: "memory")
#define CP_WAIT0  asm volatile("cp.async.wait_group 0;" ::: "memory")
#define CP_WAIT1  asm volatile("cp.async.wait_group 1;" ::: "memory")

// MUFU exp: e^x = 2^(x*log2e) via ex2.approx (~2^-21 rel err)
__device__ __forceinline__ float fexpm(float x) {
    float r;
    asm("ex2.approx.ftz.f32 %0, %1;" : "=f"(r) : "f"(x * LOG2E));
    return r;
}

// ---------------- scratch (no allocs allowed) ----------------
__device__ uint32_t g_qb[(size_t)NL*QKH/2];     // bf16x2 packed activations
__device__ uint32_t g_kb[(size_t)NL*QKH/2];
__device__ uint32_t g_vb[(size_t)NL*QKH/2];     // V rows pre-masked (zero where !mask)
__device__ uint32_t g_h1b[(size_t)NL*HID/2];
__device__ uint32_t g_featb[(size_t)NL*FEAT/2];
__device__ uint32_t g_xb[(size_t)NL*DD/2];
__device__ uint32_t g_tb[(size_t)NL*QK/2];
__device__ float    g_y[(size_t)NL*OUTD];
// bf16 weights [k][n] (converted once per launch)
__device__ uint32_t g_wq[DD*QKH/2];
__device__ uint32_t g_wk[DD*QKH/2];
__device__ uint32_t g_wv[DD*QKH/2];
__device__ uint32_t g_wse[QK*QKH/2];
__device__ uint32_t g_w1[FEAT*HID/2];
__device__ uint32_t g_w2[HID*OUTD/2];

// ============================================================
// K-1: convert weights + x  fp32 -> packed bf16
// ============================================================
__global__ void k_cvtw(const float* __restrict__ Wq, const float* __restrict__ Wk,
                       const float* __restrict__ Wv, const float* __restrict__ seW2,
                       const float* __restrict__ W1, const float* __restrict__ W2,
                       const float* __restrict__ x)
{
    const int m = blockIdx.y;
    const float* src; uint32_t* dst; int ng;   // groups of 8 elements
    switch (m) {
        case 0: src = Wq;   dst = g_wq;  ng = DD*QKH/8;   break;
        case 1: src = Wk;   dst = g_wk;  ng = DD*QKH/8;   break;
        case 2: src = Wv;   dst = g_wv;  ng = DD*QKH/8;   break;
        case 3: src = seW2; dst = g_wse; ng = QK*QKH/8;   break;
        case 4: src = W1;   dst = g_w1;  ng = FEAT*HID/8; break;
        case 5: src = W2;   dst = g_w2;  ng = HID*OUTD/8; break;
        default:src = x;    dst = g_xb;  ng = NL*DD/8;    break;
    }
    int i = blockIdx.x * blockDim.x + threadIdx.x;
    if (i >= ng) return;
    float4 a = ((const float4*)src)[2*i];
    float4 b = ((const float4*)src)[2*i+1];
    uint4 w;
    w.x = bf2(a.x, a.y); w.y = bf2(a.z, a.w);
    w.z = bf2(b.x, b.y); w.w = bf2(b.z, b.w);
    ((uint4*)dst)[i] = w;
}

// ============================================================
// K0: t = relu(pos_CA @ se_W1 + se_b1) -> packed bf16 (4096x32)
// ============================================================
__global__ void k_spat(const float* __restrict__ posCA,
                       const float* __restrict__ seW1,
                       const float* __restrict__ seb1)
{
    int r = blockIdx.x * blockDim.x + threadIdx.x;
    if (r >= NL) return;
    float p0 = posCA[r*3+0], p1 = posCA[r*3+1], p2 = posCA[r*3+2];
#pragma unroll
    for (int j = 0; j < QK/2; j++) {
        int c0 = 2*j, c1 = 2*j+1;
        float v0 = seb1[c0] + p0*seW1[c0] + p1*seW1[QK + c0] + p2*seW1[2*QK + c0];
        float v1 = seb1[c1] + p0*seW1[c1] + p1*seW1[QK + c1] + p2*seW1[2*QK + c1];
        g_tb[(size_t)r*(QK/2) + j] = bf2(fmaxf(v0, 0.0f), fmaxf(v1, 0.0f));
    }
}

// ============================================================
// GEMM: BM=128, BN=64, BK=32, 8 warps (2M x 4N), m16n8k16.
// cp.async double-buffered; A fragments via ldmatrix.x4.
// ============================================================
__device__ __forceinline__ void loadA_async(uint32_t (*As)[20], const uint32_t* A,
                                            int ldp, int bm, int kcp, int tid)
{
    int r = tid >> 1;
    int h = (tid & 1) * 8;
    const uint32_t* p = A + (size_t)(bm + r) * ldp + kcp + h;
    cpa16(&As[r][h],     p);
    cpa16(&As[r][h + 4], p + 4);
}
__device__ __forceinline__ void loadB_async(__nv_bfloat16 (*Bs16)[72], const uint32_t* W,
                                            int ldn2, int bn, int kc, int tid)
{
    int k  = tid >> 3;
    int n0 = (tid & 7) * 8;
    cpa16(&Bs16[k][n0], W + (size_t)(kc + k) * ldn2 + (bn + n0)/2);
}

__device__ __forceinline__ void mma_chunk_bf(const uint32_t (*As)[20],
                                             const __nv_bfloat16 (*Bs16)[72],
                                             float acc[4][2][4], int warpM, int warpN,
                                             int lane)
{
    const int i16 = lane & 15;
    const int hi4 = (lane >> 4) * 4;   // u32 (pair) offset for ldsm4 col window
#pragma unroll
    for (int s = 0; s < 2; s++) {
        uint2 b[2];
#pragma unroll
        for (int nt = 0; nt < 2; nt++)
            b[nt] = ldsm2t(&Bs16[s*16 + i16][warpN*16 + nt*8]);
#pragma unroll
        for (int mt = 0; mt < 4; mt++) {
            uint4 a = ldsm4(&As[warpM*64 + mt*16 + i16][s*8 + hi4]);
#pragma unroll
            for (int nt = 0; nt < 2; nt++)
                mma_bf16(acc[mt][nt], a.x, a.y, a.z, a.w, b[nt].x, b[nt].y);
        }
    }
}

#define GEMM_PROLOG                                                  \
    __shared__ __align__(16) uint32_t AsB[2][128][20];               \
    __shared__ __align__(16) __nv_bfloat16 BsB[2][32][72];           \
    const int tid  = threadIdx.x;                                    \
    const int wid  = tid >> 5;                                       \
    const int lane = tid & 31;                                       \
    const int g    = lane >> 2, t4 = lane & 3;                       \
    const int warpM = wid >> 2, warpN = wid & 3;                     \
    float acc[4][2][4];                                              \
    _Pragma("unroll") for (int i = 0; i < 4; i++)                    \
    _Pragma("unroll") for (int j = 0; j < 2; j++)                    \
    _Pragma("unroll") for (int q = 0; q < 4; q++) acc[i][j][q] = 0.0f;

// ============================================================
// K1: fused QKV projection (4096 x 1536, K=256).
// q: + t@se_W2 + se_b2 (NO prescale).  v: pre-masked by row mask.
// ============================================================
__global__ void __launch_bounds__(256) k_qkv(const float* __restrict__ seb2,
                                             const int* __restrict__ mask)
{
    const int bm  = blockIdx.x * 128;
    const int mat = blockIdx.y >> 3;           // 0=q 1=k 2=v
    const int bn  = (blockIdx.y & 7) * 64;
    const uint32_t* W = (mat == 0) ? g_wq : (mat == 1) ? g_wk : g_wv;

    GEMM_PROLOG
    (void)g; (void)t4;

    const int nchunks = (mat == 0) ? 9 : 8;
    loadA_async(AsB[0], g_xb, DD/2, bm, 0, tid);
    loadB_async(BsB[0], W, QKH/2, bn, 0, tid);
    CP_COMMIT;
    for (int ch = 0; ch < nchunks; ch++) {
        if (ch + 1 < nchunks) {
            int nb = (ch + 1) & 1;
            if (ch + 1 < 8) {
                loadA_async(AsB[nb], g_xb, DD/2, bm, (ch+1)*16, tid);
                loadB_async(BsB[nb], W, QKH/2, bn, (ch+1)*32, tid);
            } else {
                loadA_async(AsB[nb], g_tb, QK/2, bm, 0, tid);
                loadB_async(BsB[nb], g_wse, QKH/2, bn, 0, tid);
            }
            CP_COMMIT;
            CP_WAIT1;
        } else {
            CP_WAIT0;
        }
        __syncthreads();
        mma_chunk_bf(AsB[ch & 1], BsB[ch & 1], acc, warpM, warpN, lane);
        __syncthreads();
    }

    uint32_t* dst = (mat == 0) ? g_qb : (mat == 1) ? g_kb : g_vb;
    const int gg = lane >> 2, tt = lane & 3;
#pragma unroll
    for (int mt = 0; mt < 4; mt++) {
#pragma unroll
        for (int nt = 0; nt < 2; nt++) {
            int R0 = bm + warpM*64 + mt*16 + gg;
            int C  = bn + warpN*16 + nt*8 + 2*tt;
            float v0 = acc[mt][nt][0], v1 = acc[mt][nt][1];
            float v2 = acc[mt][nt][2], v3 = acc[mt][nt][3];
            if (mat == 0) {
                float bx = seb2[C], by = seb2[C+1];
                v0 += bx; v1 += by; v2 += bx; v3 += by;
            } else if (mat == 2) {
                float m0 = mask[R0]     ? 1.0f : 0.0f;
                float m1 = mask[R0 + 8] ? 1.0f : 0.0f;
                v0 *= m0; v1 *= m0; v2 *= m1; v3 *= m1;
            }
            dst[(size_t)R0*(QKH/2)     + C/2] = bf2(v0, v1);
            dst[(size_t)(R0+8)*(QKH/2) + C/2] = bf2(v2, v3);
        }
    }
}

// ============================================================
// K2: bf16 TC attention, q-split, cp.async pipeline,
// register-resident P, Q in regs, MUFU ex2 exp, mask folded
// into V. Grid (HH, NB, 2): block = 256 q-rows, 8 warps.
// ============================================================
__global__ void __launch_bounds__(256, 2) k_attn(
    const float* __restrict__ posCA,
    const float* __restrict__ posCB,
    const float* __restrict__ frame,
    const int*   __restrict__ mask)
{
    extern __shared__ __align__(16) uint32_t smu[];
    uint32_t (*Qs)[20] = (uint32_t (*)[20])smu;                              // [256][20]
    uint32_t (*KsB)[32][20] = (uint32_t (*)[32][20])(smu + 256*20);          // [2][32][20]
    __nv_bfloat16 (*VsB)[32][72] = (__nv_bfloat16 (*)[32][72])(smu + 256*20 + 2*32*20); // [2][32][72]
    float* mkf = (float*)(smu + 256*20 + 2*32*20 + 2*32*36);                 // [512]

    const int h  = blockIdx.x;
    const int b  = blockIdx.y;
    const int qh = blockIdx.z;
    const int tid = threadIdx.x;
    const int w = tid >> 5, lane = tid & 31;
    const int g = lane >> 2, t4 = lane & 3;
    const int i16 = lane & 15;
    const int krow = lane & 7, khalf = (lane >> 3) & 1;   // ldmatrix.x2 addressing
    const int qbase = qh * 256;

    // ---- group 0: Q + K/V chunk 0 ----
#pragma unroll
    for (int it = 0; it < 4; it++) {
        int idx = tid + 256*it;
        int r = idx >> 2, c4 = idx & 3;
        cpa16(&Qs[r][c4*4], g_qb + ((size_t)b*LL + qbase + r)*(QKH/2) + h*(QK/2) + c4*4);
    }
    if (tid < 128) {
        int j = tid >> 2, c4 = tid & 3;
        cpa16(&VsB[0][j][c4*8], g_vb + ((size_t)b*LL + j)*(QKH/2) + h*(QK/2) + c4*4);
    } else {
        int t = tid - 128;
        int j = t >> 2, c4 = t & 3;
        cpa16(&KsB[0][j][c4*4], g_kb + ((size_t)b*LL + j)*(QKH/2) + h*(QK/2) + c4*4);
    }
    CP_COMMIT;
    if (tid < 32) {
        int j = tid;
        float mj = mask[b*LL + j] ? 1.0f : 0.0f;
        const float* pp = posCB + ((size_t)b*LL + j)*3;
        VsB[0][j][32] = __float2bfloat16(mj * pp[0]);
        VsB[0][j][33] = __float2bfloat16(mj * pp[1]);
        VsB[0][j][34] = __float2bfloat16(mj * pp[2]);
        VsB[0][j][35] = __float2bfloat16(mj);
        VsB[0][j][36] = __float2bfloat16(0.0f);
        VsB[0][j][37] = __float2bfloat16(0.0f);
        VsB[0][j][38] = __float2bfloat16(0.0f);
        VsB[0][j][39] = __float2bfloat16(0.0f);
    }
    mkf[tid]       = mask[b*LL + tid]       ? 1.0f : 0.0f;
    mkf[tid + 256] = mask[b*LL + tid + 256] ? 1.0f : 0.0f;

    // ---- group 1: K/V chunk 1 ----
    if (tid < 128) {
        int j = tid >> 2, c4 = tid & 3;
        cpa16(&VsB[1][j][c4*8], g_vb + ((size_t)b*LL + 32 + j)*(QKH/2) + h*(QK/2) + c4*4);
    } else {
        int t = tid - 128;
        int j = t >> 2, c4 = t & 3;
        cpa16(&KsB[1][j][c4*4], g_kb + ((size_t)b*LL + 32 + j)*(QKH/2) + h*(QK/2) + c4*4);
    }
    CP_COMMIT;
    if (tid < 32) {
        int j = tid;
        float mj = mask[b*LL + 32 + j] ? 1.0f : 0.0f;
        const float* pp = posCB + ((size_t)b*LL + 32 + j)*3;
        VsB[1][j][32] = __float2bfloat16(mj * pp[0]);
        VsB[1][j][33] = __float2bfloat16(mj * pp[1]);
        VsB[1][j][34] = __float2bfloat16(mj * pp[2]);
        VsB[1][j][35] = __float2bfloat16(mj);
        VsB[1][j][36] = __float2bfloat16(0.0f);
        VsB[1][j][37] = __float2bfloat16(0.0f);
        VsB[1][j][38] = __float2bfloat16(0.0f);
        VsB[1][j][39] = __float2bfloat16(0.0f);
    }
    CP_WAIT1;        // group 0 (Q + chunk 0) complete
    __syncthreads();

    // ---- hoist Q fragments into registers (chunk-invariant) ----
    uint32_t qreg[2][2][4];
#pragma unroll
    for (int mt = 0; mt < 2; mt++) {
        const int rb = w*32 + mt*16;
#pragma unroll
        for (int s = 0; s < 2; s++) {
            qreg[mt][s][0] = Qs[rb+g][s*8+t4];
            qreg[mt][s][1] = Qs[rb+g+8][s*8+t4];
            qreg[mt][s][2] = Qs[rb+g][s*8+t4+4];
            qreg[mt][s][3] = Qs[rb+g+8][s*8+t4+4];
        }
    }

    float acc[2][5][4];
#pragma unroll
    for (int i = 0; i < 2; i++)
#pragma unroll
        for (int j = 0; j < 5; j++)
#pragma unroll
            for (int q = 0; q < 4; q++) acc[i][j][q] = 0.0f;

    for (int ch = 0; ch < 16; ch++) {
        const int cb = ch & 1;

        // K fragments via ldmatrix.x2 (non-trans on [n][k] layout)
        uint32_t kb[4][2][2];
#pragma unroll
        for (int nt = 0; nt < 4; nt++)
#pragma unroll
            for (int s = 0; s < 2; s++) {
                uint2 t = ldsm2(&KsB[cb][8*nt + krow][s*8 + khalf*4]);
                kb[nt][s][0] = t.x;
                kb[nt][s][1] = t.y;
            }
        // V fragments
        uint2 vb[2][5];
#pragma unroll
        for (int s = 0; s < 2; s++)
#pragma unroll
            for (int nt = 0; nt < 5; nt++)
                vb[s][nt] = ldsm2t(&VsB[cb][s*16 + i16][nt*8]);

#pragma unroll
        for (int mt = 0; mt < 2; mt++) {
            // ---- S = Q @ K^T ----
            float S[4][4];
#pragma unroll
            for (int nt = 0; nt < 4; nt++)
#pragma unroll
                for (int q = 0; q < 4; q++) S[nt][q] = 0.0f;
#pragma unroll
            for (int s = 0; s < 2; s++)
#pragma unroll
                for (int nt = 0; nt < 4; nt++)
                    mma_bf16(S[nt], qreg[mt][s][0], qreg[mt][s][1],
                             qreg[mt][s][2], qreg[mt][s][3],
                             kb[nt][s][0], kb[nt][s][1]);
            // ---- P = exp(S) via MUFU (mask folded into V), A fragments ----
            uint32_t pa[2][4];
#pragma unroll
            for (int hf = 0; hf < 2; hf++) {
                const int na = 2*hf, nb2 = 2*hf + 1;
                pa[hf][0] = bf2(fexpm(S[na][0]),  fexpm(S[na][1]));
                pa[hf][1] = bf2(fexpm(S[na][2]),  fexpm(S[na][3]));
                pa[hf][2] = bf2(fexpm(S[nb2][0]), fexpm(S[nb2][1]));
                pa[hf][3] = bf2(fexpm(S[nb2][2]), fexpm(S[nb2][3]));
            }
            // ---- O += P @ Vaug ----
#pragma unroll
            for (int s = 0; s < 2; s++)
#pragma unroll
                for (int nt = 0; nt < 5; nt++)
                    mma_bf16(acc[mt][nt], pa[s][0], pa[s][1], pa[s][2], pa[s][3],
                             vb[s][nt].x, vb[s][nt].y);
        }

        __syncthreads();   // all warps done reading buffer cb
        if (ch + 2 < 16) {
            const int j2 = (ch + 2) * 32;
            if (tid < 128) {
                int j = tid >> 2, c4 = tid & 3;
                cpa16(&VsB[cb][j][c4*8], g_vb + ((size_t)b*LL + j2 + j)*(QKH/2) + h*(QK/2) + c4*4);
            } else {
                int t = tid - 128;
                int j = t >> 2, c4 = t & 3;
                cpa16(&KsB[cb][j][c4*4], g_kb + ((size_t)b*LL + j2 + j)*(QKH/2) + h*(QK/2) + c4*4);
            }
            CP_COMMIT;
            if (tid < 32) {
                int j = tid;
                float mj = mask[b*LL + j2 + j] ? 1.0f : 0.0f;
                const float* pp = posCB + ((size_t)b*LL + j2 + j)*3;
                VsB[cb][j][32] = __float2bfloat16(mj * pp[0]);
                VsB[cb][j][33] = __float2bfloat16(mj * pp[1]);
                VsB[cb][j][34] = __float2bfloat16(mj * pp[2]);
                VsB[cb][j][35] = __float2bfloat16(mj);
                VsB[cb][j][36] = __float2bfloat16(0.0f);
                VsB[cb][j][37] = __float2bfloat16(0.0f);
                VsB[cb][j][38] = __float2bfloat16(0.0f);
                VsB[cb][j][39] = __float2bfloat16(0.0f);
            }
        }
        if (ch + 1 < 16) {
            if (ch + 2 < 16) { CP_WAIT1; } else { CP_WAIT0; }
            __syncthreads();
        }
    }

    // ---- epilogue (fp32 math, bf16 feature stores) ----
#pragma unroll
    for (int mt = 0; mt < 2; mt++) {
#pragma unroll
        for (int half = 0; half < 2; half++) {
            const int rloc = w*32 + mt*16 + g + half*8;
            const size_t grow = (size_t)b*LL + qbase + rloc;
            float c_lo = half ? acc[mt][4][2] : acc[mt][4][0];
            float c_hi = half ? acc[mt][4][3] : acc[mt][4][1];
            const int qb = lane & ~3;
            float ap0 = __shfl_sync(0xffffffffu, c_lo, qb + 0);
            float ap1 = __shfl_sync(0xffffffffu, c_hi, qb + 0);
            float ap2 = __shfl_sync(0xffffffffu, c_lo, qb + 1);
            float s   = __shfl_sync(0xffffffffu, c_hi, qb + 1);
            const bool ok = (mkf[qbase + rloc] != 0.0f) && (s > 0.0f);
            const float inv = ok ? 1.0f / s : 0.0f;
            uint32_t* fr = g_featb + grow * (FEAT/2);
            __nv_bfloat16* fr16 = (__nv_bfloat16*)fr;
#pragma unroll
            for (int nt = 0; nt < 4; nt++) {
                float v0 = half ? acc[mt][nt][2] : acc[mt][nt][0];
                float v1 = half ? acc[mt][nt][3] : acc[mt][nt][1];
                fr[h*16 + nt*4 + t4] = bf2(v0*inv, v1*inv);
            }
            if (t4 == 0) {
                if (!ok) {
                    fr16[512+h*3+0] = __float2bfloat16(0.0f);
                    fr16[512+h*3+1] = __float2bfloat16(0.0f);
                    fr16[512+h*3+2] = __float2bfloat16(0.0f);
                    fr16[560+h]     = __float2bfloat16(0.0f);
                    fr16[576+h*3+0] = __float2bfloat16(0.0f);
                    fr16[576+h*3+1] = __float2bfloat16(0.0f);
                    fr16[576+h*3+2] = __float2bfloat16(0.0f);
                    fr16[624+h]     = __float2bfloat16(0.0f);
                } else {
                    float a0 = ap0*inv - posCA[grow*3+0];
                    float a1 = ap1*inv - posCA[grow*3+1];
                    float a2 = ap2*inv - posCA[grow*3+2];
                    const float* F = frame + grow * 9;
                    float pt0 = F[0]*a0 + F[1]*a1 + F[2]*a2;
                    float pt1 = F[3]*a0 + F[4]*a1 + F[5]*a2;
                    float pt2 = F[6]*a0 + F[7]*a1 + F[8]*a2;
                    float dist = sqrtf(a0*a0 + a1*a1 + a2*a2);
                    float pn   = sqrtf(pt0*pt0 + pt1*pt1 + pt2*pt2);
                    float id   = 1.0f / (pn + 1e-10f);
                    float ang  = atan2f(pt1, pt0);
                    fr16[512+h*3+0] = __float2bfloat16(pt0);
                    fr16[512+h*3+1] = __float2bfloat16(pt1);
                    fr16[512+h*3+2] = __float2bfloat16(pt2);
                    fr16[560+h]     = __float2bfloat16(dist);
                    fr16[576+h*3+0] = __float2bfloat16(pt0*id);
                    fr16[576+h*3+1] = __float2bfloat16(pt1*id);
                    fr16[576+h*3+2] = __float2bfloat16(pt2*id);
                    fr16[624+h]     = __float2bfloat16(ang);
                }
            }
        }
    }
}

// ============================================================
// K3a: h1 = relu(feat @ W1 + b1) -> packed bf16 (4096x512,K=640)
// ============================================================
__global__ void __launch_bounds__(256) k_mlp1(const float* __restrict__ b1)
{
    const int bm = blockIdx.x * 128;
    const int bn = blockIdx.y * 64;

    GEMM_PROLOG

    const int NCH = FEAT/32;   // 20
    loadA_async(AsB[0], g_featb, FEAT/2, bm, 0, tid);
    loadB_async(BsB[0], g_w1, HID/2, bn, 0, tid);
    CP_COMMIT;
    for (int ch = 0; ch < NCH; ch++) {
        if (ch + 1 < NCH) {
            int nb = (ch + 1) & 1;
            loadA_async(AsB[nb], g_featb, FEAT/2, bm, (ch+1)*16, tid);
            loadB_async(BsB[nb], g_w1, HID/2, bn, (ch+1)*32, tid);
            CP_COMMIT;
            CP_WAIT1;
        } else {
            CP_WAIT0;
        }
        __syncthreads();
        mma_chunk_bf(AsB[ch & 1], BsB[ch & 1], acc, warpM, warpN, lane);
        __syncthreads();
    }

#pragma unroll
    for (int mt = 0; mt < 4; mt++) {
#pragma unroll
        for (int nt = 0; nt < 2; nt++) {
            int R0 = bm + warpM*64 + mt*16 + g;
            int C  = bn + warpN*16 + nt*8 + 2*t4;
            float bx = b1[C], by = b1[C+1];
            g_h1b[(size_t)R0*(HID/2)     + C/2] =
                bf2(fmaxf(acc[mt][nt][0] + bx, 0.f), fmaxf(acc[mt][nt][1] + by, 0.f));
            g_h1b[(size_t)(R0+8)*(HID/2) + C/2] =
                bf2(fmaxf(acc[mt][nt][2] + bx, 0.f), fmaxf(acc[mt][nt][3] + by, 0.f));
        }
    }
}

// ============================================================
// K3b: y = x + mask*(h1 @ W2 + b2)   (4096x256, K=512)
// ============================================================
__global__ void __launch_bounds__(256) k_mlp2(
    const float* __restrict__ x, const float* __restrict__ b2,
    const int* __restrict__ mask)
{
    const int bm = blockIdx.x * 128;
    const int bn = blockIdx.y * 64;

    GEMM_PROLOG

    const int NCH = HID/32;   // 16
    loadA_async(AsB[0], g_h1b, HID/2, bm, 0, tid);
    loadB_async(BsB[0], g_w2, OUTD/2, bn, 0, tid);
    CP_COMMIT;
    for (int ch = 0; ch < NCH; ch++) {
        if (ch + 1 < NCH) {
            int nb = (ch + 1) & 1;
            loadA_async(AsB[nb], g_h1b, HID/2, bm, (ch+1)*16, tid);
            loadB_async(BsB[nb], g_w2, OUTD/2, bn, (ch+1)*32, tid);
            CP_COMMIT;
            CP_WAIT1;
        } else {
            CP_WAIT0;
        }
        __syncthreads();
        mma_chunk_bf(AsB[ch & 1], BsB[ch & 1], acc, warpM, warpN, lane);
        __syncthreads();
    }

#pragma unroll
    for (int mt = 0; mt < 4; mt++) {
#pragma unroll
        for (int nt = 0; nt < 2; nt++) {
            int R0 = bm + warpM*64 + mt*16 + g;
            int C  = bn + warpN*16 + nt*8 + 2*t4;
            float bx = b2[C], by = b2[C+1];
#pragma unroll
            for (int half = 0; half < 2; half++) {
                int R = R0 + half*8;
                float2 xv = *(const float2*)&x[(size_t)R*OUTD + C];
                float2 v;
                if (mask[R]) {
                    v.x = xv.x + acc[mt][nt][2*half+0] + bx;
                    v.y = xv.y + acc[mt][nt][2*half+1] + by;
                } else {
                    v = xv;
                }
                *(float2*)&g_y[(size_t)R*OUTD + C] = v;
            }
        }
    }
}

// ============================================================
// K4: LayerNorm. One warp per row.
// ============================================================
__global__ void __launch_bounds__(256) k_ln(
    const float* __restrict__ lng, const float* __restrict__ lnb,
    float* __restrict__ out)
{
    const int wid  = threadIdx.x >> 5;
    const int lane = threadIdx.x & 31;
    const int row  = blockIdx.x * 8 + wid;

    const float* yr = g_y + (size_t)row * OUTD;
    float yv[8];
    float ssum = 0.0f, ssq = 0.0f;
#pragma unroll
    for (int t = 0; t < 2; t++) {
        float4 v = *(const float4*)&yr[lane*4 + t*128];
        yv[t*4+0]=v.x; yv[t*4+1]=v.y; yv[t*4+2]=v.z; yv[t*4+3]=v.w;
        ssum += v.x+v.y+v.z+v.w;
        ssq  += v.x*v.x+v.y*v.y+v.z*v.z+v.w*v.w;
    }
#pragma unroll
    for (int off = 16; off > 0; off >>= 1) {
        ssum += __shfl_xor_sync(0xFFFFFFFF, ssum, off);
        ssq  += __shfl_xor_sync(0xFFFFFFFF, ssq,  off);
    }
    float mu  = ssum * (1.0f / OUTD);
    float var = ssq * (1.0f / OUTD) - mu * mu;
    float rs  = rsqrtf(var + 1e-5f);
#pragma unroll
    for (int t = 0; t < 2; t++) {
        int c = lane*4 + t*128;
        float4 gg = *(const float4*)&lng[c];
        float4 bb = *(const float4*)&lnb[c];
        float4 o;
        o.x = (yv[t*4+0]-mu)*rs*gg.x + bb.x;
        o.y = (yv[t*4+1]-mu)*rs*gg.y + bb.y;
        o.z = (yv[t*4+2]-mu)*rs*gg.z + bb.z;
        o.w = (yv[t*4+3]-mu)*rs*gg.w + bb.w;
        *(float4*)&out[(size_t)row*OUTD + c] = o;
    }
}

// ============================================================
extern "C" void kernel_launch(void* const* d_in, const int* in_sizes, int n_in,
                              void* d_out, int out_size)
{
    const float* x     = (const float*)d_in[0];
    const float* posCA = (const float*)d_in[1];
    const float* posCB = (const float*)d_in[2];
    const float* frame = (const float*)d_in[3];
    const int*   mask  = (const int*)  d_in[4];
    const float* Wq    = (const float*)d_in[5];
    const float* Wk    = (const float*)d_in[6];
    const float* Wv    = (const float*)d_in[7];
    const float* seW1  = (const float*)d_in[8];
    const float* seb1  = (const float*)d_in[9];
    const float* seW2  = (const float*)d_in[10];
    const float* seb2  = (const float*)d_in[11];
    const float* otW1  = (const float*)d_in[12];
    const float* otb1  = (const float*)d_in[13];
    const float* otW2  = (const float*)d_in[14];
    const float* otb2  = (const float*)d_in[15];
    const float* lng   = (const float*)d_in[16];
    const float* lnb   = (const float*)d_in[17];
    float* out = (float*)d_out;

    // Qs + 2xKs (u32) + 2xVs (halves) + mkf
    const int smem_attn = (256*20 + 2*32*20) * 4 + 2*32*72*2 + 512*4;  // 36864
    cudaFuncSetAttribute(k_attn, cudaFuncAttributeMaxDynamicSharedMemorySize, smem_attn);

    k_cvtw<<<dim3(512, 7), 256>>>(Wq, Wk, Wv, seW2, otW1, otW2, x);
    k_spat<<<NL/128, 128>>>(posCA, seW1, seb1);
    k_qkv<<<dim3(NL/128, 24), 256>>>(seb2, mask);
    k_attn<<<dim3(HH, NB, 2), 256, smem_attn>>>(posCA, posCB, frame, mask);
    k_mlp1<<<dim3(NL/128, HID/64),  256>>>(otb1);
    k_mlp2<<<dim3(NL/128, OUTD/64), 256>>>(x, otb2, mask);
    k_ln<<<NL/8, 256>>>(lng, lnb, out);
}